// round 10
// baseline (speedup 1.0000x reference)
#include <cuda_runtime.h>

#define DIM 128
#define NH  8
#define MAXN 50176
#define MAXT 1048576   // max edges incl. self loops
#define FULL 0xffffffffu

typedef unsigned long long u64;

// ---------------- scratch (no allocations allowed) ----------------
__device__ float g_h[MAXN * DIM];
__device__ float g_x2[MAXN * DIM];
__device__ float g_asrc[MAXN * NH];
__device__ float g_adst[MAXN * NH];
__device__ int   g_cnt[MAXN + 1];   // zero at load; scan pass restores zeros
__device__ int   g_row[MAXN + 1];
__device__ int   g_cur[MAXN];
__device__ int   g_bsum[256];
__device__ int   g_csrc[MAXT];

__device__ __forceinline__ float leaky(float v) { return v > 0.f ? v : 0.2f * v; }

// packed fp32x2 helpers (sm_100+; ptxas never auto-fuses these)
__device__ __forceinline__ u64 splat2(float x) {
    u64 r; asm("mov.b64 %0, {%1, %1};" : "=l"(r) : "f"(x)); return r;
}
__device__ __forceinline__ u64 ffma2(u64 a, u64 b, u64 c) {
    u64 d; asm("fma.rn.f32x2 %0, %1, %2, %3;" : "=l"(d) : "l"(a), "l"(b), "l"(c)); return d;
}
__device__ __forceinline__ float2 unpack2(u64 v) {
    float2 f; asm("mov.b64 {%0, %1}, %2;" : "=f"(f.x), "=f"(f.y) : "l"(v)); return f;
}

// ---- C[N,128] = A[N,128] * B[128,128], FFMA2 loop, fused attn epilogue.
// Blocks [gemmBlocks, gridDim) instead run the dst-degree histogram (layer 1 only).
__global__ void gemm128(const float* __restrict__ A, const float* __restrict__ B,
                        const float* __restrict__ atts, const float* __restrict__ attd,
                        float* __restrict__ Cm, float* __restrict__ asrc,
                        float* __restrict__ adst, int N,
                        const int* __restrict__ ei, int E, int* __restrict__ cnt,
                        int gemmBlocks) {
    const int bid = blockIdx.x;
    if (bid >= gemmBlocks) {
        int stride = (gridDim.x - gemmBlocks) * blockDim.x;
        for (int e = (bid - gemmBlocks) * blockDim.x + threadIdx.x; e < E; e += stride)
            atomicAdd(&cnt[ei[E + e]], 1);
        return;
    }

    __shared__ float As[8][128];
    __shared__ float Bs[8][128];
    const int tid = threadIdx.x;           // 256 threads
    const int tx = tid & 15;
    const int ty = tid >> 4;
    const int rowBase = bid * 128;
    const int arow  = tid >> 1;
    const int akoff = (tid & 1) * 4;
    const int brow  = tid >> 5;
    const int bcol  = (tid & 31) * 4;

    u64 acc2[8][4];
#pragma unroll
    for (int i = 0; i < 8; i++)
#pragma unroll
        for (int j = 0; j < 4; j++) acc2[i][j] = 0ull;

    for (int k0 = 0; k0 < 128; k0 += 8) {
        float4 av = make_float4(0.f, 0.f, 0.f, 0.f);
        int gr = rowBase + arow;
        if (gr < N) av = *(const float4*)&A[(size_t)gr * DIM + k0 + akoff];
        As[akoff + 0][arow] = av.x;
        As[akoff + 1][arow] = av.y;
        As[akoff + 2][arow] = av.z;
        As[akoff + 3][arow] = av.w;
        *(float4*)&Bs[brow][bcol] = *(const float4*)&B[(size_t)(k0 + brow) * DIM + bcol];
        __syncthreads();
#pragma unroll
        for (int kr = 0; kr < 8; kr++) {
            float4 a0 = *(const float4*)&As[kr][ty * 8];
            float4 a1 = *(const float4*)&As[kr][ty * 8 + 4];
            float a[8] = { a0.x, a0.y, a0.z, a0.w, a1.x, a1.y, a1.z, a1.w };
            ulonglong2 bq0 = *(const ulonglong2*)&Bs[kr][tx * 8];
            ulonglong2 bq1 = *(const ulonglong2*)&Bs[kr][tx * 8 + 4];
            u64 bp[4] = { bq0.x, bq0.y, bq1.x, bq1.y };
#pragma unroll
            for (int i = 0; i < 8; i++) {
                u64 as2 = splat2(a[i]);
#pragma unroll
                for (int jp = 0; jp < 4; jp++)
                    acc2[i][jp] = ffma2(as2, bp[jp], acc2[i][jp]);
            }
        }
        __syncthreads();
    }

    // unpack, store C, fused attention epilogue
    const int head = tx >> 1;
    float sv[8], dv[8];
#pragma unroll
    for (int j = 0; j < 8; j++) {
        int off = (tx & 1) * 8 + j;
        sv[j] = atts[head * 16 + off];
        dv[j] = attd[head * 16 + off];
    }
#pragma unroll
    for (int i = 0; i < 8; i++) {
        float2 c0 = unpack2(acc2[i][0]);
        float2 c1 = unpack2(acc2[i][1]);
        float2 c2 = unpack2(acc2[i][2]);
        float2 c3 = unpack2(acc2[i][3]);
        float c[8] = { c0.x, c0.y, c1.x, c1.y, c2.x, c2.y, c3.x, c3.y };
        int gr = rowBase + ty * 8 + i;
        if (gr < N) {
            *(float4*)&Cm[(size_t)gr * DIM + tx * 8]     = make_float4(c[0], c[1], c[2], c[3]);
            *(float4*)&Cm[(size_t)gr * DIM + tx * 8 + 4] = make_float4(c[4], c[5], c[6], c[7]);
        }
        float ss = 0.f, sd = 0.f;
#pragma unroll
        for (int j = 0; j < 8; j++) { ss += c[j] * sv[j]; sd += c[j] * dv[j]; }
        ss += __shfl_xor_sync(FULL, ss, 1);
        sd += __shfl_xor_sync(FULL, sd, 1);
        if ((tx & 1) == 0 && gr < N) {
            asrc[gr * NH + head] = ss;
            adst[gr * NH + head] = sd;
        }
    }
}

// ---------------- CSR build (coalesced 2-kernel scan) ----------------
__global__ void scan1_k(const int* __restrict__ cnt, int N, int* __restrict__ bsum) {
    __shared__ int sh[256];
    int t = threadIdx.x;
    int i = blockIdx.x * 256 + t;
    sh[t] = (i < N) ? cnt[i] + 1 : 0;
    __syncthreads();
    for (int off = 128; off > 0; off >>= 1) {
        if (t < off) sh[t] += sh[t + off];
        __syncthreads();
    }
    if (t == 0) bsum[blockIdx.x] = sh[0];
}

__global__ void scan3_k(int* __restrict__ cnt, int N, int nb,
                        const int* __restrict__ bsum, int* __restrict__ row,
                        int* __restrict__ cur, int* __restrict__ csrc) {
    __shared__ int sh[256];
    __shared__ int bb[256];
    int t = threadIdx.x;
    int i = blockIdx.x * 256 + t;

    bb[t] = (t < nb && t < (int)blockIdx.x) ? bsum[t] : 0;
    __syncthreads();
    for (int off = 128; off > 0; off >>= 1) {
        if (t < off) bb[t] += bb[t + off];
        __syncthreads();
    }
    const int boff = bb[0];
    __syncthreads();

    int v = (i < N) ? cnt[i] + 1 : 0;
    sh[t] = v;
    __syncthreads();
    for (int off = 1; off < 256; off <<= 1) {
        int x = (t >= off) ? sh[t - off] : 0;
        __syncthreads();
        sh[t] += x;
        __syncthreads();
    }
    int excl = sh[t] - v + boff;
    if (i < N) {
        row[i] = excl;
        csrc[excl] = i;       // self loop first
        cur[i] = excl + 1;
        cnt[i] = 0;           // restore zero-invariant
    }
    if (i == N - 1) row[N] = excl + v;
}

// two edges per thread (int2 loads; E is even) -> MLP=2 on the atomic chain
__global__ void scatter_k(const int* __restrict__ ei, int E,
                          int* __restrict__ cur, int* __restrict__ csrc) {
    int t = blockIdx.x * blockDim.x + threadIdx.x;
    int e0 = t * 2;
    if (e0 >= E) return;
    int2 s = *(const int2*)&ei[e0];
    int2 d = *(const int2*)&ei[E + e0];
    int p0 = atomicAdd(&cur[d.x], 1);
    int p1 = atomicAdd(&cur[d.y], 1);
    csrc[p0] = s.x;
    csrc[p1] = s.y;
}

// ---- fused per-node softmax + aggregation: warp-batched, full-lane gathers ----
// one warp per destination node; lane l owns output cols [4l,4l+4), head hsel=l>>2.
// asrc gathers: 4 edges x 8 heads per step -> all 32 lanes load concurrently.
__global__ void gat_node_k(const int* __restrict__ csrc, const int* __restrict__ row,
                           const float* __restrict__ asrc, const float* __restrict__ adst,
                           const float* __restrict__ hf, const float* __restrict__ bias,
                           float* __restrict__ out, int N, int do_relu) {
    int warp = (blockIdx.x * blockDim.x + threadIdx.x) >> 5;
    int lane = threadIdx.x & 31;
    if (warp >= N) return;
    const int node = warp;
    const int beg = row[node], end = row[node + 1];

    const int head = lane & 7;        // head this lane loads asrc for
    const int egrp = lane >> 3;       // edge slot (e % 4) this lane covers
    const int hsel = lane >> 2;       // head of my output columns
    const float ad = adst[node * NH + head];

    float den = 0.f;                  // per-lane partial denominator
    float a0 = 0.f, a1 = 0.f, a2 = 0.f, a3 = 0.f;

    for (int base = beg; base < end; base += 32) {
        const int cntc = min(32, end - base);
        // warp-parallel index fetch (coalesced)
        int sIdx = (base + lane < end) ? csrc[base + lane] : 0;

        for (int g = 0; g * 4 < cntc; g++) {
            // 4 edges' attention coefficients, all 32 lanes loading at once
            int eg = g * 4 + egrp;
            int se = __shfl_sync(FULL, sIdx, eg);
            float v = 0.f;
            if (eg < cntc)
                v = __expf(leaky(asrc[se * NH + head] + ad));
            den += v;
            // aggregate the (up to) 4 edges; gathers are independent -> MLP=4
            const int lim = min(4, cntc - g * 4);
#pragma unroll 4
            for (int j = 0; j < lim; j++) {
                int s = __shfl_sync(FULL, sIdx, g * 4 + j);
                float w = __shfl_sync(FULL, v, j * 8 + hsel);
                float4 hv = *(const float4*)&hf[(size_t)s * DIM + lane * 4];
                a0 += w * hv.x; a1 += w * hv.y; a2 += w * hv.z; a3 += w * hv.w;
            }
        }
    }

    // reduce per-lane partial denominators across the 4 edge-slot groups
    den += __shfl_xor_sync(FULL, den, 8);
    den += __shfl_xor_sync(FULL, den, 16);
    // lane (hsel) now holds the denominator for head hsel
    float dd = __shfl_sync(FULL, den, hsel);
    float inv = 1.f / dd;
    float4 bv = *(const float4*)&bias[lane * 4];
    float4 o = make_float4(a0 * inv + bv.x, a1 * inv + bv.y,
                           a2 * inv + bv.z, a3 * inv + bv.w);
    if (do_relu) {
        o.x = fmaxf(o.x, 0.f); o.y = fmaxf(o.y, 0.f);
        o.z = fmaxf(o.z, 0.f); o.w = fmaxf(o.w, 0.f);
    }
    *(float4*)&out[(size_t)node * DIM + lane * 4] = o;
}

// ---------------- host ----------------
extern "C" void kernel_launch(void* const* d_in, const int* in_sizes, int n_in,
                              void* d_out, int out_size) {
    const float* x   = (const float*)d_in[0];
    const int*   ei  = (const int*)d_in[1];   // int32 (JAX x64 disabled)
    const float* W1  = (const float*)d_in[2];
    const float* as1 = (const float*)d_in[3];
    const float* ad1 = (const float*)d_in[4];
    const float* b1  = (const float*)d_in[5];
    const float* W2  = (const float*)d_in[6];
    const float* as2 = (const float*)d_in[7];
    const float* ad2 = (const float*)d_in[8];
    const float* b2  = (const float*)d_in[9];
    float* out = (float*)d_out;

    int N = in_sizes[0] / DIM;
    int E = in_sizes[1] / 2;

    float *hbuf, *x2, *asrc, *adst;
    int *cnt, *row, *cur, *bsum, *csrc;
    cudaGetSymbolAddress((void**)&hbuf, g_h);
    cudaGetSymbolAddress((void**)&x2,   g_x2);
    cudaGetSymbolAddress((void**)&asrc, g_asrc);
    cudaGetSymbolAddress((void**)&adst, g_adst);
    cudaGetSymbolAddress((void**)&cnt,  g_cnt);
    cudaGetSymbolAddress((void**)&row,  g_row);
    cudaGetSymbolAddress((void**)&cur,  g_cur);
    cudaGetSymbolAddress((void**)&bsum, g_bsum);
    cudaGetSymbolAddress((void**)&csrc, g_csrc);

    const int GB = (N + 127) / 128;   // gemm blocks
    const int HB = 128;               // histogram blocks (layer 1 only)
    const int nb = (N + 255) / 256;
    const int ET = (E + 1) / 2;       // scatter threads (2 edges each)

    // layer-1 GEMM + (overlapped) degree histogram
    gemm128<<<GB + HB, 256>>>(x, W1, as1, ad1, hbuf, asrc, adst, N, ei, E, cnt, GB);
    // CSR build
    scan1_k<<<nb, 256>>>(cnt, N, bsum);
    scan3_k<<<nb, 256>>>(cnt, N, nb, bsum, row, cur, csrc);
    scatter_k<<<(ET + 255) / 256, 256>>>(ei, E, cur, csrc);
    // layer 1 aggregation (fused ReLU) -> x2
    gat_node_k<<<(N + 7) / 8, 256>>>(csrc, row, asrc, adst, hbuf, b1, x2, N, 1);
    // layer 2
    gemm128<<<GB, 256>>>(x2, W2, as2, ad2, hbuf, asrc, adst, N, ei, 0, cnt, GB);
    gat_node_k<<<(N + 7) / 8, 256>>>(csrc, row, asrc, adst, hbuf, b2, out, N, 0);
}

// round 12
// speedup vs baseline: 1.1151x; 1.1151x over previous
#include <cuda_runtime.h>

#define DIM 128
#define NH  8
#define MAXN 50176
#define MAXT 1048576   // max edges incl. self loops
#define FULL 0xffffffffu

typedef unsigned long long u64;

// ---------------- scratch (no allocations allowed) ----------------
__device__ float g_h[MAXN * DIM];
__device__ float g_x2[MAXN * DIM];
__device__ float g_asrc[MAXN * NH];
__device__ float g_adst[MAXN * NH];
__device__ int   g_cnt[MAXN + 1];   // zero at load; scan pass restores zeros
__device__ int   g_row[MAXN + 1];
__device__ int   g_bsum[256];
__device__ int   g_rank[MAXT];      // per-edge rank within its dst neighborhood
__device__ int   g_csrc[MAXT];

__device__ __forceinline__ float leaky(float v) { return v > 0.f ? v : 0.2f * v; }

// packed fp32x2 helpers (sm_100+; ptxas never auto-fuses these)
__device__ __forceinline__ u64 splat2(float x) {
    u64 r; asm("mov.b64 %0, {%1, %1};" : "=l"(r) : "f"(x)); return r;
}
__device__ __forceinline__ u64 ffma2(u64 a, u64 b, u64 c) {
    u64 d; asm("fma.rn.f32x2 %0, %1, %2, %3;" : "=l"(d) : "l"(a), "l"(b), "l"(c)); return d;
}
__device__ __forceinline__ float2 unpack2(u64 v) {
    float2 f; asm("mov.b64 {%0, %1}, %2;" : "=f"(f.x), "=f"(f.y) : "l"(v)); return f;
}

// ---- C[N,128] = A[N,128] * B[128,128], FFMA2 loop, fused attn epilogue.
// Blocks [gemmBlocks, gridDim) instead run the dst-degree histogram (layer 1
// only), which also records each edge's rank -> later scatter needs no atomics.
__global__ void gemm128(const float* __restrict__ A, const float* __restrict__ B,
                        const float* __restrict__ atts, const float* __restrict__ attd,
                        float* __restrict__ Cm, float* __restrict__ asrc,
                        float* __restrict__ adst, int N,
                        const int* __restrict__ ei, int E, int* __restrict__ cnt,
                        int* __restrict__ rank, int gemmBlocks) {
    const int bid = blockIdx.x;
    if (bid >= gemmBlocks) {
        int stride = (gridDim.x - gemmBlocks) * blockDim.x;
        for (int e = (bid - gemmBlocks) * blockDim.x + threadIdx.x; e < E; e += stride)
            rank[e] = atomicAdd(&cnt[ei[E + e]], 1);
        return;
    }

    __shared__ float As[8][128];
    __shared__ float Bs[8][128];
    const int tid = threadIdx.x;           // 256 threads
    const int tx = tid & 15;
    const int ty = tid >> 4;
    const int rowBase = bid * 128;
    const int arow  = tid >> 1;
    const int akoff = (tid & 1) * 4;
    const int brow  = tid >> 5;
    const int bcol  = (tid & 31) * 4;

    u64 acc2[8][4];
#pragma unroll
    for (int i = 0; i < 8; i++)
#pragma unroll
        for (int j = 0; j < 4; j++) acc2[i][j] = 0ull;

    for (int k0 = 0; k0 < 128; k0 += 8) {
        float4 av = make_float4(0.f, 0.f, 0.f, 0.f);
        int gr = rowBase + arow;
        if (gr < N) av = *(const float4*)&A[(size_t)gr * DIM + k0 + akoff];
        As[akoff + 0][arow] = av.x;
        As[akoff + 1][arow] = av.y;
        As[akoff + 2][arow] = av.z;
        As[akoff + 3][arow] = av.w;
        *(float4*)&Bs[brow][bcol] = *(const float4*)&B[(size_t)(k0 + brow) * DIM + bcol];
        __syncthreads();
#pragma unroll
        for (int kr = 0; kr < 8; kr++) {
            float4 a0 = *(const float4*)&As[kr][ty * 8];
            float4 a1 = *(const float4*)&As[kr][ty * 8 + 4];
            float a[8] = { a0.x, a0.y, a0.z, a0.w, a1.x, a1.y, a1.z, a1.w };
            ulonglong2 bq0 = *(const ulonglong2*)&Bs[kr][tx * 8];
            ulonglong2 bq1 = *(const ulonglong2*)&Bs[kr][tx * 8 + 4];
            u64 bp[4] = { bq0.x, bq0.y, bq1.x, bq1.y };
#pragma unroll
            for (int i = 0; i < 8; i++) {
                u64 as2 = splat2(a[i]);
#pragma unroll
                for (int jp = 0; jp < 4; jp++)
                    acc2[i][jp] = ffma2(as2, bp[jp], acc2[i][jp]);
            }
        }
        __syncthreads();
    }

    // unpack, store C, fused attention epilogue
    const int head = tx >> 1;
    float sv[8], dv[8];
#pragma unroll
    for (int j = 0; j < 8; j++) {
        int off = (tx & 1) * 8 + j;
        sv[j] = atts[head * 16 + off];
        dv[j] = attd[head * 16 + off];
    }
#pragma unroll
    for (int i = 0; i < 8; i++) {
        float2 c0 = unpack2(acc2[i][0]);
        float2 c1 = unpack2(acc2[i][1]);
        float2 c2 = unpack2(acc2[i][2]);
        float2 c3 = unpack2(acc2[i][3]);
        float c[8] = { c0.x, c0.y, c1.x, c1.y, c2.x, c2.y, c3.x, c3.y };
        int gr = rowBase + ty * 8 + i;
        if (gr < N) {
            *(float4*)&Cm[(size_t)gr * DIM + tx * 8]     = make_float4(c[0], c[1], c[2], c[3]);
            *(float4*)&Cm[(size_t)gr * DIM + tx * 8 + 4] = make_float4(c[4], c[5], c[6], c[7]);
        }
        float ss = 0.f, sd = 0.f;
#pragma unroll
        for (int j = 0; j < 8; j++) { ss += c[j] * sv[j]; sd += c[j] * dv[j]; }
        ss += __shfl_xor_sync(FULL, ss, 1);
        sd += __shfl_xor_sync(FULL, sd, 1);
        if ((tx & 1) == 0 && gr < N) {
            asrc[gr * NH + head] = ss;
            adst[gr * NH + head] = sd;
        }
    }
}

// ---------------- CSR build (coalesced 2-kernel scan) ----------------
__global__ void scan1_k(const int* __restrict__ cnt, int N, int* __restrict__ bsum) {
    __shared__ int sh[256];
    int t = threadIdx.x;
    int i = blockIdx.x * 256 + t;
    sh[t] = (i < N) ? cnt[i] + 1 : 0;
    __syncthreads();
    for (int off = 128; off > 0; off >>= 1) {
        if (t < off) sh[t] += sh[t + off];
        __syncthreads();
    }
    if (t == 0) bsum[blockIdx.x] = sh[0];
}

__global__ void scan3_k(int* __restrict__ cnt, int N, int nb,
                        const int* __restrict__ bsum, int* __restrict__ row,
                        int* __restrict__ csrc) {
    __shared__ int sh[256];
    __shared__ int bb[256];
    int t = threadIdx.x;
    int i = blockIdx.x * 256 + t;

    bb[t] = (t < nb && t < (int)blockIdx.x) ? bsum[t] : 0;
    __syncthreads();
    for (int off = 128; off > 0; off >>= 1) {
        if (t < off) bb[t] += bb[t + off];
        __syncthreads();
    }
    const int boff = bb[0];
    __syncthreads();

    int v = (i < N) ? cnt[i] + 1 : 0;
    sh[t] = v;
    __syncthreads();
    for (int off = 1; off < 256; off <<= 1) {
        int x = (t >= off) ? sh[t - off] : 0;
        __syncthreads();
        sh[t] += x;
        __syncthreads();
    }
    int excl = sh[t] - v + boff;
    if (i < N) {
        row[i] = excl;
        csrc[excl] = i;       // self loop first (deterministic slot)
        cnt[i] = 0;           // restore zero-invariant
    }
    if (i == N - 1) row[N] = excl + v;
}

// atomic-free scatter: position = row[dst] + 1 + precomputed rank
__global__ void scatter_k(const int* __restrict__ ei, int E,
                          const int* __restrict__ row, const int* __restrict__ rank,
                          int* __restrict__ csrc) {
    int e = blockIdx.x * blockDim.x + threadIdx.x;
    if (e >= E) return;
    int s = ei[e], d = ei[E + e];
    csrc[row[d] + 1 + rank[e]] = s;
}

// ---- fused per-node softmax + aggregation (single pass, 2x unrolled) ----
// one warp per destination node; lane l owns output cols [4l, 4l+4), head l>>2
__global__ void gat_node_k(const int* __restrict__ csrc, const int* __restrict__ row,
                           const float* __restrict__ asrc, const float* __restrict__ adst,
                           const float* __restrict__ hf, const float* __restrict__ bias,
                           float* __restrict__ out, int N, int do_relu) {
    int warp = (blockIdx.x * blockDim.x + threadIdx.x) >> 5;
    int lane = threadIdx.x & 31;
    if (warp >= N) return;
    const int node = warp;
    const int beg = row[node], end = row[node + 1];

    const float ad = (lane < NH) ? adst[node * NH + lane] : 0.f;
    const int hsel = lane >> 2;

    float den = 0.f;
    float a0 = 0.f, a1 = 0.f, a2 = 0.f, a3 = 0.f;
    int e = beg;
    for (; e + 1 < end; e += 2) {
        int s0 = csrc[e], s1 = csrc[e + 1];
        float v0 = 0.f, v1 = 0.f;
        if (lane < NH) {
            v0 = __expf(leaky(asrc[s0 * NH + lane] + ad));
            v1 = __expf(leaky(asrc[s1 * NH + lane] + ad));
        }
        den += v0 + v1;
        float w0 = __shfl_sync(FULL, v0, hsel);
        float w1 = __shfl_sync(FULL, v1, hsel);
        float4 h0 = *(const float4*)&hf[(size_t)s0 * DIM + lane * 4];
        float4 h1 = *(const float4*)&hf[(size_t)s1 * DIM + lane * 4];
        a0 += w0 * h0.x + w1 * h1.x;
        a1 += w0 * h0.y + w1 * h1.y;
        a2 += w0 * h0.z + w1 * h1.z;
        a3 += w0 * h0.w + w1 * h1.w;
    }
    if (e < end) {
        int s = csrc[e];
        float v = 0.f;
        if (lane < NH) v = __expf(leaky(asrc[s * NH + lane] + ad));
        den += v;
        float w = __shfl_sync(FULL, v, hsel);
        float4 hv = *(const float4*)&hf[(size_t)s * DIM + lane * 4];
        a0 += w * hv.x; a1 += w * hv.y; a2 += w * hv.z; a3 += w * hv.w;
    }
    float dd = __shfl_sync(FULL, den, hsel);
    float inv = 1.f / dd;
    float4 bv = *(const float4*)&bias[lane * 4];
    float4 o = make_float4(a0 * inv + bv.x, a1 * inv + bv.y,
                           a2 * inv + bv.z, a3 * inv + bv.w);
    if (do_relu) {
        o.x = fmaxf(o.x, 0.f); o.y = fmaxf(o.y, 0.f);
        o.z = fmaxf(o.z, 0.f); o.w = fmaxf(o.w, 0.f);
    }
    *(float4*)&out[(size_t)node * DIM + lane * 4] = o;
}

// ---------------- host ----------------
extern "C" void kernel_launch(void* const* d_in, const int* in_sizes, int n_in,
                              void* d_out, int out_size) {
    const float* x   = (const float*)d_in[0];
    const int*   ei  = (const int*)d_in[1];   // int32 (JAX x64 disabled)
    const float* W1  = (const float*)d_in[2];
    const float* as1 = (const float*)d_in[3];
    const float* ad1 = (const float*)d_in[4];
    const float* b1  = (const float*)d_in[5];
    const float* W2  = (const float*)d_in[6];
    const float* as2 = (const float*)d_in[7];
    const float* ad2 = (const float*)d_in[8];
    const float* b2  = (const float*)d_in[9];
    float* out = (float*)d_out;

    int N = in_sizes[0] / DIM;
    int E = in_sizes[1] / 2;

    float *hbuf, *x2, *asrc, *adst;
    int *cnt, *row, *bsum, *rank, *csrc;
    cudaGetSymbolAddress((void**)&hbuf, g_h);
    cudaGetSymbolAddress((void**)&x2,   g_x2);
    cudaGetSymbolAddress((void**)&asrc, g_asrc);
    cudaGetSymbolAddress((void**)&adst, g_adst);
    cudaGetSymbolAddress((void**)&cnt,  g_cnt);
    cudaGetSymbolAddress((void**)&row,  g_row);
    cudaGetSymbolAddress((void**)&bsum, g_bsum);
    cudaGetSymbolAddress((void**)&rank, g_rank);
    cudaGetSymbolAddress((void**)&csrc, g_csrc);

    const int GB = (N + 127) / 128;   // gemm blocks
    const int HB = 128;               // histogram blocks (layer 1 only)
    const int nb = (N + 255) / 256;

    // layer-1 GEMM + (overlapped) degree histogram with rank recording
    gemm128<<<GB + HB, 256>>>(x, W1, as1, ad1, hbuf, asrc, adst, N, ei, E, cnt, rank, GB);
    // CSR build (scan re-zeroes cnt); scatter is atomic-free
    scan1_k<<<nb, 256>>>(cnt, N, bsum);
    scan3_k<<<nb, 256>>>(cnt, N, nb, bsum, row, csrc);
    scatter_k<<<(E + 255) / 256, 256>>>(ei, E, row, rank, csrc);
    // layer 1 aggregation (fused ReLU) -> x2
    gat_node_k<<<(N + 7) / 8, 256>>>(csrc, row, asrc, adst, hbuf, b1, x2, N, 1);
    // layer 2
    gemm128<<<GB, 256>>>(x2, W2, as2, ad2, hbuf, asrc, adst, N, ei, 0, cnt, rank, GB);
    gat_node_k<<<(N + 7) / 8, 256>>>(csrc, row, asrc, adst, hbuf, b2, out, N, 0);
}

// round 13
// speedup vs baseline: 1.2373x; 1.1096x over previous
#include <cuda_runtime.h>

#define DIM 128
#define NH  8
#define MAXN 50176
#define MAXT 1048576   // max edges incl. self loops
#define FULL 0xffffffffu

typedef unsigned long long u64;

// ---------------- scratch (no allocations allowed) ----------------
__device__ float g_h[MAXN * DIM];
__device__ float g_x2[MAXN * DIM];
__device__ float g_asrc[MAXN * NH];
__device__ float g_adst[MAXN * NH];
__device__ int   g_cnt[MAXN + 1];   // zero at load; scan pass restores zeros
__device__ int   g_row[MAXN + 1];
__device__ int   g_bsum[256];
__device__ int   g_rank[MAXT];      // per-edge rank within its dst neighborhood
__device__ int   g_csrc[MAXT];

__device__ __forceinline__ float leaky(float v) { return v > 0.f ? v : 0.2f * v; }

// packed fp32x2 helpers (sm_100+; ptxas never auto-fuses these)
__device__ __forceinline__ u64 splat2(float x) {
    u64 r; asm("mov.b64 %0, {%1, %1};" : "=l"(r) : "f"(x)); return r;
}
__device__ __forceinline__ u64 ffma2(u64 a, u64 b, u64 c) {
    u64 d; asm("fma.rn.f32x2 %0, %1, %2, %3;" : "=l"(d) : "l"(a), "l"(b), "l"(c)); return d;
}
__device__ __forceinline__ float2 unpack2(u64 v) {
    float2 f; asm("mov.b64 {%0, %1}, %2;" : "=f"(f.x), "=f"(f.y) : "l"(v)); return f;
}

// ---- C[N,128] = A[N,128] * B[128,128], FFMA2 loop, fused attn epilogue.
// Blocks [gemmBlocks, gridDim) instead run the dst-degree histogram (layer 1
// only), recording each edge's rank -> later scatter needs no atomics.
__global__ void gemm128(const float* __restrict__ A, const float* __restrict__ B,
                        const float* __restrict__ atts, const float* __restrict__ attd,
                        float* __restrict__ Cm, float* __restrict__ asrc,
                        float* __restrict__ adst, int N,
                        const int* __restrict__ ei, int E, int* __restrict__ cnt,
                        int* __restrict__ rank, int gemmBlocks) {
    const int bid = blockIdx.x;
    if (bid >= gemmBlocks) {
        int stride = (gridDim.x - gemmBlocks) * blockDim.x;
        for (int e = (bid - gemmBlocks) * blockDim.x + threadIdx.x; e < E; e += stride)
            rank[e] = atomicAdd(&cnt[ei[E + e]], 1);
        return;
    }

    __shared__ float As[8][128];
    __shared__ float Bs[8][128];
    const int tid = threadIdx.x;           // 256 threads
    const int tx = tid & 15;
    const int ty = tid >> 4;
    const int rowBase = bid * 128;
    const int arow  = tid >> 1;
    const int akoff = (tid & 1) * 4;
    const int brow  = tid >> 5;
    const int bcol  = (tid & 31) * 4;

    u64 acc2[8][4];
#pragma unroll
    for (int i = 0; i < 8; i++)
#pragma unroll
        for (int j = 0; j < 4; j++) acc2[i][j] = 0ull;

    for (int k0 = 0; k0 < 128; k0 += 8) {
        float4 av = make_float4(0.f, 0.f, 0.f, 0.f);
        int gr = rowBase + arow;
        if (gr < N) av = *(const float4*)&A[(size_t)gr * DIM + k0 + akoff];
        As[akoff + 0][arow] = av.x;
        As[akoff + 1][arow] = av.y;
        As[akoff + 2][arow] = av.z;
        As[akoff + 3][arow] = av.w;
        *(float4*)&Bs[brow][bcol] = *(const float4*)&B[(size_t)(k0 + brow) * DIM + bcol];
        __syncthreads();
#pragma unroll
        for (int kr = 0; kr < 8; kr++) {
            float4 a0 = *(const float4*)&As[kr][ty * 8];
            float4 a1 = *(const float4*)&As[kr][ty * 8 + 4];
            float a[8] = { a0.x, a0.y, a0.z, a0.w, a1.x, a1.y, a1.z, a1.w };
            ulonglong2 bq0 = *(const ulonglong2*)&Bs[kr][tx * 8];
            ulonglong2 bq1 = *(const ulonglong2*)&Bs[kr][tx * 8 + 4];
            u64 bp[4] = { bq0.x, bq0.y, bq1.x, bq1.y };
#pragma unroll
            for (int i = 0; i < 8; i++) {
                u64 as2 = splat2(a[i]);
#pragma unroll
                for (int jp = 0; jp < 4; jp++)
                    acc2[i][jp] = ffma2(as2, bp[jp], acc2[i][jp]);
            }
        }
        __syncthreads();
    }

    // unpack, store C, fused attention epilogue
    const int head = tx >> 1;
    float sv[8], dv[8];
#pragma unroll
    for (int j = 0; j < 8; j++) {
        int off = (tx & 1) * 8 + j;
        sv[j] = atts[head * 16 + off];
        dv[j] = attd[head * 16 + off];
    }
#pragma unroll
    for (int i = 0; i < 8; i++) {
        float2 c0 = unpack2(acc2[i][0]);
        float2 c1 = unpack2(acc2[i][1]);
        float2 c2 = unpack2(acc2[i][2]);
        float2 c3 = unpack2(acc2[i][3]);
        float c[8] = { c0.x, c0.y, c1.x, c1.y, c2.x, c2.y, c3.x, c3.y };
        int gr = rowBase + ty * 8 + i;
        if (gr < N) {
            *(float4*)&Cm[(size_t)gr * DIM + tx * 8]     = make_float4(c[0], c[1], c[2], c[3]);
            *(float4*)&Cm[(size_t)gr * DIM + tx * 8 + 4] = make_float4(c[4], c[5], c[6], c[7]);
        }
        float ss = 0.f, sd = 0.f;
#pragma unroll
        for (int j = 0; j < 8; j++) { ss += c[j] * sv[j]; sd += c[j] * dv[j]; }
        ss += __shfl_xor_sync(FULL, ss, 1);
        sd += __shfl_xor_sync(FULL, sd, 1);
        if ((tx & 1) == 0 && gr < N) {
            asrc[gr * NH + head] = ss;
            adst[gr * NH + head] = sd;
        }
    }
}

// ---------------- CSR build (coalesced 2-kernel scan) ----------------
__global__ void scan1_k(const int* __restrict__ cnt, int N, int* __restrict__ bsum) {
    __shared__ int sh[256];
    int t = threadIdx.x;
    int i = blockIdx.x * 256 + t;
    sh[t] = (i < N) ? cnt[i] + 1 : 0;
    __syncthreads();
    for (int off = 128; off > 0; off >>= 1) {
        if (t < off) sh[t] += sh[t + off];
        __syncthreads();
    }
    if (t == 0) bsum[blockIdx.x] = sh[0];
}

__global__ void scan3_k(int* __restrict__ cnt, int N, int nb,
                        const int* __restrict__ bsum, int* __restrict__ row,
                        int* __restrict__ csrc) {
    __shared__ int sh[256];
    __shared__ int bb[256];
    int t = threadIdx.x;
    int i = blockIdx.x * 256 + t;

    bb[t] = (t < nb && t < (int)blockIdx.x) ? bsum[t] : 0;
    __syncthreads();
    for (int off = 128; off > 0; off >>= 1) {
        if (t < off) bb[t] += bb[t + off];
        __syncthreads();
    }
    const int boff = bb[0];
    __syncthreads();

    int v = (i < N) ? cnt[i] + 1 : 0;
    sh[t] = v;
    __syncthreads();
    for (int off = 1; off < 256; off <<= 1) {
        int x = (t >= off) ? sh[t - off] : 0;
        __syncthreads();
        sh[t] += x;
        __syncthreads();
    }
    int excl = sh[t] - v + boff;
    if (i < N) {
        row[i] = excl;
        csrc[excl] = i;       // self loop first (deterministic slot)
        cnt[i] = 0;           // restore zero-invariant
    }
    if (i == N - 1) row[N] = excl + v;
}

// atomic-free scatter: position = row[dst] + 1 + precomputed rank
__global__ void scatter_k(const int* __restrict__ ei, int E,
                          const int* __restrict__ row, const int* __restrict__ rank,
                          int* __restrict__ csrc) {
    int e = blockIdx.x * blockDim.x + threadIdx.x;
    if (e >= E) return;
    int s = ei[e], d = ei[E + e];
    csrc[row[d] + 1 + rank[e]] = s;
}

// ---- fused per-node softmax + aggregation: shuffle-free inner loop ----
// one warp per destination node; lane l owns output cols [4l,4l+4), head l>>2.
// Every lane gathers its own head's asrc value (8 consecutive floats -> one
// 32B sector, broadcast) and computes exp itself: no shuffles, no predication.
// den accumulates identically in all 4 lanes of a head -> no final reduction.
__global__ void gat_node_k(const int* __restrict__ csrc, const int* __restrict__ row,
                           const float* __restrict__ asrc, const float* __restrict__ adst,
                           const float* __restrict__ hf, const float* __restrict__ bias,
                           float* __restrict__ out, int N, int do_relu) {
    int warp = (blockIdx.x * blockDim.x + threadIdx.x) >> 5;
    int lane = threadIdx.x & 31;
    if (warp >= N) return;
    const int node = warp;
    const int beg = row[node], end = row[node + 1];

    const int hsel = lane >> 2;                    // this lane's head
    const float ad = adst[node * NH + hsel];

    float den = 0.f;
    float a0 = 0.f, a1 = 0.f, a2 = 0.f, a3 = 0.f;
    int e = beg;
    for (; e + 1 < end; e += 2) {
        int s0 = csrc[e], s1 = csrc[e + 1];
        float v0 = __expf(leaky(asrc[s0 * NH + hsel] + ad));
        float v1 = __expf(leaky(asrc[s1 * NH + hsel] + ad));
        den += v0 + v1;
        float4 h0 = *(const float4*)&hf[(size_t)s0 * DIM + lane * 4];
        float4 h1 = *(const float4*)&hf[(size_t)s1 * DIM + lane * 4];
        a0 += v0 * h0.x + v1 * h1.x;
        a1 += v0 * h0.y + v1 * h1.y;
        a2 += v0 * h0.z + v1 * h1.z;
        a3 += v0 * h0.w + v1 * h1.w;
    }
    if (e < end) {
        int s = csrc[e];
        float v = __expf(leaky(asrc[s * NH + hsel] + ad));
        den += v;
        float4 hv = *(const float4*)&hf[(size_t)s * DIM + lane * 4];
        a0 += v * hv.x; a1 += v * hv.y; a2 += v * hv.z; a3 += v * hv.w;
    }
    float inv = 1.f / den;
    float4 bv = *(const float4*)&bias[lane * 4];
    float4 o = make_float4(a0 * inv + bv.x, a1 * inv + bv.y,
                           a2 * inv + bv.z, a3 * inv + bv.w);
    if (do_relu) {
        o.x = fmaxf(o.x, 0.f); o.y = fmaxf(o.y, 0.f);
        o.z = fmaxf(o.z, 0.f); o.w = fmaxf(o.w, 0.f);
    }
    *(float4*)&out[(size_t)node * DIM + lane * 4] = o;
}

// ---------------- host ----------------
extern "C" void kernel_launch(void* const* d_in, const int* in_sizes, int n_in,
                              void* d_out, int out_size) {
    const float* x   = (const float*)d_in[0];
    const int*   ei  = (const int*)d_in[1];   // int32 (JAX x64 disabled)
    const float* W1  = (const float*)d_in[2];
    const float* as1 = (const float*)d_in[3];
    const float* ad1 = (const float*)d_in[4];
    const float* b1  = (const float*)d_in[5];
    const float* W2  = (const float*)d_in[6];
    const float* as2 = (const float*)d_in[7];
    const float* ad2 = (const float*)d_in[8];
    const float* b2  = (const float*)d_in[9];
    float* out = (float*)d_out;

    int N = in_sizes[0] / DIM;
    int E = in_sizes[1] / 2;

    float *hbuf, *x2, *asrc, *adst;
    int *cnt, *row, *bsum, *rank, *csrc;
    cudaGetSymbolAddress((void**)&hbuf, g_h);
    cudaGetSymbolAddress((void**)&x2,   g_x2);
    cudaGetSymbolAddress((void**)&asrc, g_asrc);
    cudaGetSymbolAddress((void**)&adst, g_adst);
    cudaGetSymbolAddress((void**)&cnt,  g_cnt);
    cudaGetSymbolAddress((void**)&row,  g_row);
    cudaGetSymbolAddress((void**)&bsum, g_bsum);
    cudaGetSymbolAddress((void**)&rank, g_rank);
    cudaGetSymbolAddress((void**)&csrc, g_csrc);

    const int GB = (N + 127) / 128;   // gemm blocks
    const int HB = 128;               // histogram blocks (layer 1 only)
    const int nb = (N + 255) / 256;

    // layer-1 GEMM + (overlapped) degree histogram with rank recording
    gemm128<<<GB + HB, 256>>>(x, W1, as1, ad1, hbuf, asrc, adst, N, ei, E, cnt, rank, GB);
    // CSR build (scan re-zeroes cnt); scatter is atomic-free
    scan1_k<<<nb, 256>>>(cnt, N, bsum);
    scan3_k<<<nb, 256>>>(cnt, N, nb, bsum, row, csrc);
    scatter_k<<<(E + 255) / 256, 256>>>(ei, E, row, rank, csrc);
    // layer 1 aggregation (fused ReLU) -> x2
    gat_node_k<<<(N + 7) / 8, 256>>>(csrc, row, asrc, adst, hbuf, b1, x2, N, 1);
    // layer 2
    gemm128<<<GB, 256>>>(x2, W2, as2, ad2, hbuf, asrc, adst, N, ei, 0, cnt, rank, GB);
    gat_node_k<<<(N + 7) / 8, 256>>>(csrc, row, asrc, adst, hbuf, b2, out, N, 0);
}

// round 17
// speedup vs baseline: 1.2896x; 1.0423x over previous
#include <cuda_runtime.h>

#define DIM 128
#define NH  8
#define MAXN 50176
#define MAXT 1048576   // max edges incl. self loops
#define FULL 0xffffffffu

typedef unsigned long long u64;

// ---------------- scratch (no allocations allowed) ----------------
__device__ float g_h[MAXN * DIM];
__device__ float g_x2[MAXN * DIM];
__device__ float g_asrc[MAXN * NH];
__device__ float g_adst[MAXN * NH];
__device__ int   g_cnt[MAXN + 1];   // zero at load; scan pass restores zeros
__device__ int   g_row[MAXN + 1];
__device__ int   g_bsum[256];
__device__ int   g_rank[MAXT];      // per-edge rank within its dst neighborhood
__device__ int   g_csrc[MAXT];

__device__ __forceinline__ float leaky(float v) { return v > 0.f ? v : 0.2f * v; }

// packed fp32x2 helpers (sm_100+; ptxas never auto-fuses these)
__device__ __forceinline__ u64 splat2(float x) {
    u64 r; asm("mov.b64 %0, {%1, %1};" : "=l"(r) : "f"(x)); return r;
}
__device__ __forceinline__ u64 ffma2(u64 a, u64 b, u64 c) {
    u64 d; asm("fma.rn.f32x2 %0, %1, %2, %3;" : "=l"(d) : "l"(a), "l"(b), "l"(c)); return d;
}
__device__ __forceinline__ float2 unpack2(u64 v) {
    float2 f; asm("mov.b64 {%0, %1}, %2;" : "=f"(f.x), "=f"(f.y) : "l"(v)); return f;
}

// ---- C[N,128] = A[N,128] * B[128,128], FFMA2 loop, fused attn epilogue.
// Blocks [gemmBlocks, gridDim) instead run the dst-degree histogram (layer 1
// only), recording each edge's rank -> later scatter needs no atomics.
__global__ void gemm128(const float* __restrict__ A, const float* __restrict__ B,
                        const float* __restrict__ atts, const float* __restrict__ attd,
                        float* __restrict__ Cm, float* __restrict__ asrc,
                        float* __restrict__ adst, int N,
                        const int* __restrict__ ei, int E, int* __restrict__ cnt,
                        int* __restrict__ rank, int gemmBlocks) {
    const int bid = blockIdx.x;
    if (bid >= gemmBlocks) {
        int stride = (gridDim.x - gemmBlocks) * blockDim.x;
        for (int e = (bid - gemmBlocks) * blockDim.x + threadIdx.x; e < E; e += stride)
            rank[e] = atomicAdd(&cnt[ei[E + e]], 1);
        return;
    }

    __shared__ float As[8][128];
    __shared__ float Bs[8][128];
    const int tid = threadIdx.x;           // 256 threads
    const int tx = tid & 15;
    const int ty = tid >> 4;
    const int rowBase = bid * 128;
    const int arow  = tid >> 1;
    const int akoff = (tid & 1) * 4;
    const int brow  = tid >> 5;
    const int bcol  = (tid & 31) * 4;

    u64 acc2[8][4];
#pragma unroll
    for (int i = 0; i < 8; i++)
#pragma unroll
        for (int j = 0; j < 4; j++) acc2[i][j] = 0ull;

    for (int k0 = 0; k0 < 128; k0 += 8) {
        float4 av = make_float4(0.f, 0.f, 0.f, 0.f);
        int gr = rowBase + arow;
        if (gr < N) av = *(const float4*)&A[(size_t)gr * DIM + k0 + akoff];
        As[akoff + 0][arow] = av.x;
        As[akoff + 1][arow] = av.y;
        As[akoff + 2][arow] = av.z;
        As[akoff + 3][arow] = av.w;
        *(float4*)&Bs[brow][bcol] = *(const float4*)&B[(size_t)(k0 + brow) * DIM + bcol];
        __syncthreads();
#pragma unroll
        for (int kr = 0; kr < 8; kr++) {
            float4 a0 = *(const float4*)&As[kr][ty * 8];
            float4 a1 = *(const float4*)&As[kr][ty * 8 + 4];
            float a[8] = { a0.x, a0.y, a0.z, a0.w, a1.x, a1.y, a1.z, a1.w };
            ulonglong2 bq0 = *(const ulonglong2*)&Bs[kr][tx * 8];
            ulonglong2 bq1 = *(const ulonglong2*)&Bs[kr][tx * 8 + 4];
            u64 bp[4] = { bq0.x, bq0.y, bq1.x, bq1.y };
#pragma unroll
            for (int i = 0; i < 8; i++) {
                u64 as2 = splat2(a[i]);
#pragma unroll
                for (int jp = 0; jp < 4; jp++)
                    acc2[i][jp] = ffma2(as2, bp[jp], acc2[i][jp]);
            }
        }
        __syncthreads();
    }

    // unpack, store C, fused attention epilogue
    const int head = tx >> 1;
    float sv[8], dv[8];
#pragma unroll
    for (int j = 0; j < 8; j++) {
        int off = (tx & 1) * 8 + j;
        sv[j] = atts[head * 16 + off];
        dv[j] = attd[head * 16 + off];
    }
#pragma unroll
    for (int i = 0; i < 8; i++) {
        float2 c0 = unpack2(acc2[i][0]);
        float2 c1 = unpack2(acc2[i][1]);
        float2 c2 = unpack2(acc2[i][2]);
        float2 c3 = unpack2(acc2[i][3]);
        float c[8] = { c0.x, c0.y, c1.x, c1.y, c2.x, c2.y, c3.x, c3.y };
        int gr = rowBase + ty * 8 + i;
        if (gr < N) {
            *(float4*)&Cm[(size_t)gr * DIM + tx * 8]     = make_float4(c[0], c[1], c[2], c[3]);
            *(float4*)&Cm[(size_t)gr * DIM + tx * 8 + 4] = make_float4(c[4], c[5], c[6], c[7]);
        }
        float ss = 0.f, sd = 0.f;
#pragma unroll
        for (int j = 0; j < 8; j++) { ss += c[j] * sv[j]; sd += c[j] * dv[j]; }
        ss += __shfl_xor_sync(FULL, ss, 1);
        sd += __shfl_xor_sync(FULL, sd, 1);
        if ((tx & 1) == 0 && gr < N) {
            asrc[gr * NH + head] = ss;
            adst[gr * NH + head] = sd;
        }
    }
}

// ---------------- CSR build (coalesced 2-kernel scan) ----------------
__global__ void scan1_k(const int* __restrict__ cnt, int N, int* __restrict__ bsum) {
    __shared__ int sh[256];
    int t = threadIdx.x;
    int i = blockIdx.x * 256 + t;
    sh[t] = (i < N) ? cnt[i] + 1 : 0;
    __syncthreads();
    for (int off = 128; off > 0; off >>= 1) {
        if (t < off) sh[t] += sh[t + off];
        __syncthreads();
    }
    if (t == 0) bsum[blockIdx.x] = sh[0];
}

__global__ void scan3_k(int* __restrict__ cnt, int N, int nb,
                        const int* __restrict__ bsum, int* __restrict__ row,
                        int* __restrict__ csrc) {
    __shared__ int sh[256];
    __shared__ int bb[256];
    int t = threadIdx.x;
    int i = blockIdx.x * 256 + t;

    bb[t] = (t < nb && t < (int)blockIdx.x) ? bsum[t] : 0;
    __syncthreads();
    for (int off = 128; off > 0; off >>= 1) {
        if (t < off) bb[t] += bb[t + off];
        __syncthreads();
    }
    const int boff = bb[0];
    __syncthreads();

    int v = (i < N) ? cnt[i] + 1 : 0;
    sh[t] = v;
    __syncthreads();
    for (int off = 1; off < 256; off <<= 1) {
        int x = (t >= off) ? sh[t - off] : 0;
        __syncthreads();
        sh[t] += x;
        __syncthreads();
    }
    int excl = sh[t] - v + boff;
    if (i < N) {
        row[i] = excl;
        csrc[excl] = i;       // self loop first (deterministic slot)
        cnt[i] = 0;           // restore zero-invariant
    }
    if (i == N - 1) row[N] = excl + v;
}

// atomic-free scatter, 4 edges/thread: int4 loads of src+rank, 4 independent
// row[dst] gathers in flight (MLP=4).
__global__ void scatter_k(const int* __restrict__ ei, int E,
                          const int* __restrict__ row, const int* __restrict__ rank,
                          int* __restrict__ csrc) {
    int t = blockIdx.x * blockDim.x + threadIdx.x;
    int e0 = t * 4;
    if (e0 >= E) return;
    if (e0 + 3 < E) {
        int4 s = *(const int4*)&ei[e0];
        int4 r = *(const int4*)&rank[e0];
        int d0 = ei[E + e0], d1 = ei[E + e0 + 1], d2 = ei[E + e0 + 2], d3 = ei[E + e0 + 3];
        int r0 = row[d0], r1 = row[d1], r2 = row[d2], r3 = row[d3];
        csrc[r0 + 1 + r.x] = s.x;
        csrc[r1 + 1 + r.y] = s.y;
        csrc[r2 + 1 + r.z] = s.z;
        csrc[r3 + 1 + r.w] = s.w;
    } else {
        for (int e = e0; e < E; e++)
            csrc[row[ei[E + e]] + 1 + rank[e]] = ei[e];
    }
}

// ---- fused per-node softmax + aggregation: shuffle-free, 4x unrolled ----
// one warp per destination node; lane l owns output cols [4l,4l+4), head l>>2.
// Every lane gathers its own head's asrc value (one 32B sector, broadcast);
// den accumulates identically in all 4 lanes of a head -> no reductions at all.
__global__ void gat_node_k(const int* __restrict__ csrc, const int* __restrict__ row,
                           const float* __restrict__ asrc, const float* __restrict__ adst,
                           const float* __restrict__ hf, const float* __restrict__ bias,
                           float* __restrict__ out, int N, int do_relu) {
    int warp = (blockIdx.x * blockDim.x + threadIdx.x) >> 5;
    int lane = threadIdx.x & 31;
    if (warp >= N) return;
    const int node = warp;
    const int beg = row[node], end = row[node + 1];

    const int hsel = lane >> 2;                    // this lane's head
    const float ad = adst[node * NH + hsel];

    float den = 0.f;
    float a0 = 0.f, a1 = 0.f, a2 = 0.f, a3 = 0.f;
    int e = beg;
    for (; e + 3 < end; e += 4) {
        int s0 = csrc[e], s1 = csrc[e + 1], s2 = csrc[e + 2], s3 = csrc[e + 3];
        float v0 = __expf(leaky(asrc[s0 * NH + hsel] + ad));
        float v1 = __expf(leaky(asrc[s1 * NH + hsel] + ad));
        float v2 = __expf(leaky(asrc[s2 * NH + hsel] + ad));
        float v3 = __expf(leaky(asrc[s3 * NH + hsel] + ad));
        den += (v0 + v1) + (v2 + v3);
        float4 h0 = *(const float4*)&hf[(size_t)s0 * DIM + lane * 4];
        float4 h1 = *(const float4*)&hf[(size_t)s1 * DIM + lane * 4];
        float4 h2 = *(const float4*)&hf[(size_t)s2 * DIM + lane * 4];
        float4 h3 = *(const float4*)&hf[(size_t)s3 * DIM + lane * 4];
        a0 += v0 * h0.x + v1 * h1.x + v2 * h2.x + v3 * h3.x;
        a1 += v0 * h0.y + v1 * h1.y + v2 * h2.y + v3 * h3.y;
        a2 += v0 * h0.z + v1 * h1.z + v2 * h2.z + v3 * h3.z;
        a3 += v0 * h0.w + v1 * h1.w + v2 * h2.w + v3 * h3.w;
    }
    for (; e < end; e++) {
        int s = csrc[e];
        float v = __expf(leaky(asrc[s * NH + hsel] + ad));
        den += v;
        float4 hv = *(const float4*)&hf[(size_t)s * DIM + lane * 4];
        a0 += v * hv.x; a1 += v * hv.y; a2 += v * hv.z; a3 += v * hv.w;
    }
    float inv = 1.f / den;
    float4 bv = *(const float4*)&bias[lane * 4];
    float4 o = make_float4(a0 * inv + bv.x, a1 * inv + bv.y,
                           a2 * inv + bv.z, a3 * inv + bv.w);
    if (do_relu) {
        o.x = fmaxf(o.x, 0.f); o.y = fmaxf(o.y, 0.f);
        o.z = fmaxf(o.z, 0.f); o.w = fmaxf(o.w, 0.f);
    }
    *(float4*)&out[(size_t)node * DIM + lane * 4] = o;
}

// ---------------- host ----------------
extern "C" void kernel_launch(void* const* d_in, const int* in_sizes, int n_in,
                              void* d_out, int out_size) {
    const float* x   = (const float*)d_in[0];
    const int*   ei  = (const int*)d_in[1];   // int32 (JAX x64 disabled)
    const float* W1  = (const float*)d_in[2];
    const float* as1 = (const float*)d_in[3];
    const float* ad1 = (const float*)d_in[4];
    const float* b1  = (const float*)d_in[5];
    const float* W2  = (const float*)d_in[6];
    const float* as2 = (const float*)d_in[7];
    const float* ad2 = (const float*)d_in[8];
    const float* b2  = (const float*)d_in[9];
    float* out = (float*)d_out;

    int N = in_sizes[0] / DIM;
    int E = in_sizes[1] / 2;

    float *hbuf, *x2, *asrc, *adst;
    int *cnt, *row, *bsum, *rank, *csrc;
    cudaGetSymbolAddress((void**)&hbuf, g_h);
    cudaGetSymbolAddress((void**)&x2,   g_x2);
    cudaGetSymbolAddress((void**)&asrc, g_asrc);
    cudaGetSymbolAddress((void**)&adst, g_adst);
    cudaGetSymbolAddress((void**)&cnt,  g_cnt);
    cudaGetSymbolAddress((void**)&row,  g_row);
    cudaGetSymbolAddress((void**)&bsum, g_bsum);
    cudaGetSymbolAddress((void**)&rank, g_rank);
    cudaGetSymbolAddress((void**)&csrc, g_csrc);

    const int GB = (N + 127) / 128;   // gemm blocks
    const int HB = 128;               // histogram blocks (layer 1 only)
    const int nb = (N + 255) / 256;
    const int ST = (E + 3) / 4;       // scatter threads (4 edges each)

    // layer-1 GEMM + (overlapped) degree histogram with rank recording
    gemm128<<<GB + HB, 256>>>(x, W1, as1, ad1, hbuf, asrc, adst, N, ei, E, cnt, rank, GB);
    // CSR build (scan re-zeroes cnt); scatter is atomic-free
    scan1_k<<<nb, 256>>>(cnt, N, bsum);
    scan3_k<<<nb, 256>>>(cnt, N, nb, bsum, row, csrc);
    scatter_k<<<(ST + 255) / 256, 256>>>(ei, E, row, rank, csrc);
    // layer 1 aggregation (fused ReLU) -> x2
    gat_node_k<<<(N + 7) / 8, 256>>>(csrc, row, asrc, adst, hbuf, b1, x2, N, 1);
    // layer 2
    gemm128<<<GB, 256>>>(x2, W2, as2, ad2, hbuf, asrc, adst, N, ei, 0, cnt, rank, GB);
    gat_node_k<<<(N + 7) / 8, 256>>>(csrc, row, asrc, adst, hbuf, b2, out, N, 0);
}